// round 10
// baseline (speedup 1.0000x reference)
#include <cuda_runtime.h>
#include <cuda_fp16.h>
#include <math.h>
#include <stdint.h>

#define N_NODES 20000
#define MPAD    20096            // 157 * 128
#define N_EDGES 320000
#define NREL 9
#define NB 9
#define IN_DIM 128
#define HID_DIM 256
#define OUT_DIM 64
#define W1_COLS ((NREL + 1) * HID_DIM)   // 2560
#define W2_COLS ((NREL + 1) * OUT_DIM)   // 640
#define LN_EPS 1e-5f
#define NSEG (N_NODES * NREL)            // 180000 (dst, relation) segments
#define SCAN1_BLOCKS ((NSEG + 255) / 256) // 704

// ---------------- static device scratch ----------------
__device__ __half g_xh[(size_t)MPAD * IN_DIM];            // x in fp16, padded
__device__ __half g_W1t[W1_COLS * IN_DIM];                // [2560,128] K-major fp16
__device__ __half g_W2t[W2_COLS * HID_DIM];               // [640,256]  K-major fp16
__device__ __half g_Y1[(size_t)MPAD * W1_COLS];           // ~103 MB
__device__ __half g_Y2[(size_t)MPAD * W2_COLS];           // ~26 MB
__device__ __half g_h[(size_t)MPAD * HID_DIM];            // ~10 MB fp16
__device__ float  g_acc[(size_t)N_NODES * HID_DIM];       // 20.5 MB running max
__device__ int    g_counts[NSEG];
__device__ int    g_offsets[NSEG + 1];
__device__ int    g_cursor[NSEG];
__device__ int    g_rowid[N_EDGES];                       // packed src*16 + et
__device__ int    g_blocksum[SCAN1_BLOCKS];

// ---------------- helpers ----------------
static __device__ __forceinline__ uint32_t smem_u32(const void* p) {
    uint32_t a;
    asm("{ .reg .u64 t; cvta.to.shared.u64 t, %1; cvt.u32.u64 %0, t; }" : "=r"(a) : "l"(p));
    return a;
}

#if defined(__CUDA_ARCH__) && defined(__CUDA_ARCH_FEAT_SM103_ALL)
#define HAS_TCGEN05 1
#else
#define HAS_TCGEN05 0
#endif

#if HAS_TCGEN05
static __device__ __forceinline__ uint32_t elect_one() {
    uint32_t p;
    asm volatile("{\n\t.reg .pred p;\n\telect.sync _|p, 0xFFFFFFFF;\n\tselp.b32 %0, 1, 0, p;\n\t}" : "=r"(p));
    return p;
}
static __device__ __forceinline__ void mbar_init(uint32_t a, uint32_t cnt) {
    asm volatile("mbarrier.init.shared.b64 [%0], %1;" :: "r"(a), "r"(cnt) : "memory");
}
static __device__ __forceinline__ void mbar_wait(uint32_t a, uint32_t parity) {
    asm volatile(
        "{\n\t.reg .pred P;\n\t"
        "WL_%=:\n\t"
        "mbarrier.try_wait.parity.acquire.cta.shared::cta.b64 P, [%0], %1, 0x989680;\n\t"
        "@P bra WD_%=;\n\t"
        "bra WL_%=;\n\t"
        "WD_%=:\n\t}"
        :: "r"(a), "r"(parity) : "memory");
}
static __device__ __forceinline__ void tmem_alloc(uint32_t dst_smem, uint32_t ncols) {
    asm volatile("tcgen05.alloc.cta_group::1.sync.aligned.shared::cta.b32 [%0], %1;"
                 :: "r"(dst_smem), "r"(ncols) : "memory");
}
static __device__ __forceinline__ void tmem_dealloc(uint32_t tmem, uint32_t ncols) {
    asm volatile("tcgen05.dealloc.cta_group::1.sync.aligned.b32 %0, %1;" :: "r"(tmem), "r"(ncols));
}
static __device__ __forceinline__ void tmem_relinquish() {
    asm volatile("tcgen05.relinquish_alloc_permit.cta_group::1.sync.aligned;");
}
static __device__ __forceinline__ void tc_commit(uint32_t mbar) {
    asm volatile("tcgen05.commit.cta_group::1.mbarrier::arrive::one.shared::cluster.b64 [%0];"
                 :: "r"(mbar) : "memory");
}
static __device__ __forceinline__ void mma_f16_ss(uint32_t d, uint64_t adesc, uint64_t bdesc,
                                                  uint32_t idesc, uint32_t en) {
    asm volatile(
        "{\n\t.reg .pred p;\n\t"
        "setp.ne.u32 p, %5, 0;\n\t"
        "tcgen05.mma.cta_group::1.kind::f16 [%0], %1, %2, %3, {%4, %4, %4, %4}, p;\n\t}"
        :: "r"(d), "l"(adesc), "l"(bdesc), "r"(idesc), "r"(0u), "r"(en)
        : "memory");
}
// SW128 K-major SMEM descriptor: layout=SW128(2), version=1, SBO=64, LBO=1
static __device__ __forceinline__ uint64_t make_desc(uint32_t smem_addr) {
    const uint64_t base = (uint64_t(2) << 61) | (uint64_t(1) << 46) | (uint64_t(64) << 32) | (uint64_t(1) << 16);
    return base | ((uint64_t)(smem_addr >> 4) & 0x3FFF);
}
// swizzled store of 8 fp16 (16B) at (row r, fp16-col c, c % 8 == 0) of a 128x128 fp16 tile
static __device__ __forceinline__ void sts_h8(char* tile, int r, int c, uint4 v) {
    int off = ((r >> 3) + (c >> 6) * 16) * 1024 + (r & 7) * 128 + (c & 63) * 2;
    off ^= (off >> 3) & 0x70;
    *(uint4*)(tile + off) = v;
}

#define LDTM_X32(r, addr) \
    asm volatile( \
        "tcgen05.ld.sync.aligned.32x32b.x32.b32 " \
        "{%0, %1, %2, %3, %4, %5, %6, %7, " \
        " %8, %9, %10, %11, %12, %13, %14, %15, " \
        " %16, %17, %18, %19, %20, %21, %22, %23, " \
        " %24, %25, %26, %27, %28, %29, %30, %31}, [%32];" \
        : "=r"((r)[0]),  "=r"((r)[1]),  "=r"((r)[2]),  "=r"((r)[3]), \
          "=r"((r)[4]),  "=r"((r)[5]),  "=r"((r)[6]),  "=r"((r)[7]), \
          "=r"((r)[8]),  "=r"((r)[9]),  "=r"((r)[10]), "=r"((r)[11]), \
          "=r"((r)[12]), "=r"((r)[13]), "=r"((r)[14]), "=r"((r)[15]), \
          "=r"((r)[16]), "=r"((r)[17]), "=r"((r)[18]), "=r"((r)[19]), \
          "=r"((r)[20]), "=r"((r)[21]), "=r"((r)[22]), "=r"((r)[23]), \
          "=r"((r)[24]), "=r"((r)[25]), "=r"((r)[26]), "=r"((r)[27]), \
          "=r"((r)[28]), "=r"((r)[29]), "=r"((r)[30]), "=r"((r)[31]) \
        : "r"(addr))
#endif  // HAS_TCGEN05

// ---------------- x -> fp16 (padded to MPAD) ----------------
__global__ void k_x2h(const float* __restrict__ x) {
    int idx = blockIdx.x * blockDim.x + threadIdx.x;
    if (idx >= MPAD * IN_DIM / 4) return;
    int row = idx / (IN_DIM / 4);
    __half2 h0 = __half2(__float2half(0.f), __float2half(0.f)), h1 = h0;
    if (row < N_NODES) {
        float4 v = *(const float4*)(x + (size_t)idx * 4);
        h0 = __floats2half2_rn(v.x, v.y);
        h1 = __floats2half2_rn(v.z, v.w);
    }
    __half2* o = (__half2*)g_xh + (size_t)idx * 2;
    o[0] = h0; o[1] = h1;
}

// ---------------- init running-max accumulator ----------------
__global__ void k_init_acc() {
    int idx = blockIdx.x * blockDim.x + threadIdx.x;   // over N_NODES*HID_DIM/4
    if (idx < N_NODES * HID_DIM / 4) {
        ((float4*)g_acc)[idx] = make_float4(-INFINITY, -INFINITY, -INFINITY, -INFINITY);
    }
}

// ---------------- CSR build over (dst, relation) segments ----------------
__global__ void k_zero_counts() {
    int i = blockIdx.x * blockDim.x + threadIdx.x;
    if (i < NSEG) g_counts[i] = 0;
}
__global__ void k_count(const int* __restrict__ ei, const int* __restrict__ et) {
    int e = blockIdx.x * blockDim.x + threadIdx.x;
    if (e < N_EDGES) atomicAdd(&g_counts[ei[N_EDGES + e] * NREL + et[e]], 1);
}
// phase 1: block-local exclusive scan (256/block)
__global__ void __launch_bounds__(256) k_scan1() {
    int t = threadIdx.x, lane = t & 31, w = t >> 5;
    int i = blockIdx.x * 256 + t;
    int v = (i < NSEG) ? g_counts[i] : 0;
    int x = v;
#pragma unroll
    for (int o = 1; o < 32; o <<= 1) {
        int y = __shfl_up_sync(0xffffffffu, x, o);
        if (lane >= o) x += y;
    }
    __shared__ int ws[8];
    if (lane == 31) ws[w] = x;
    __syncthreads();
    int add = 0;
#pragma unroll
    for (int k = 0; k < 8; k++) add += (k < w) ? ws[k] : 0;
    if (i < NSEG) g_offsets[i] = x - v + add;
    if (t == 255) g_blocksum[blockIdx.x] = x + add;
}
// phase 2: exclusive scan of 704 block sums (one 1024-thread block)
__global__ void __launch_bounds__(1024) k_scan2() {
    int t = threadIdx.x, lane = t & 31, w = t >> 5;
    int v = (t < SCAN1_BLOCKS) ? g_blocksum[t] : 0;
    int x = v;
#pragma unroll
    for (int o = 1; o < 32; o <<= 1) {
        int y = __shfl_up_sync(0xffffffffu, x, o);
        if (lane >= o) x += y;
    }
    __shared__ int ws[32];
    if (lane == 31) ws[w] = x;
    __syncthreads();
    if (w == 0) {
        int y = ws[lane];
#pragma unroll
        for (int o = 1; o < 32; o <<= 1) {
            int z = __shfl_up_sync(0xffffffffu, y, o);
            if (lane >= o) y += z;
        }
        ws[lane] = y;
    }
    __syncthreads();
    int add = (w > 0) ? ws[w - 1] : 0;
    if (t < SCAN1_BLOCKS) g_blocksum[t] = x - v + add;
}
// phase 3: add block offsets; materialize offsets + cursor; cap entry
__global__ void __launch_bounds__(256) k_scan3() {
    int i = blockIdx.x * 256 + threadIdx.x;
    if (i < NSEG) {
        int o = g_offsets[i] + g_blocksum[blockIdx.x];
        g_offsets[i] = o;
        g_cursor[i]  = o;
    }
    if (i == 0) g_offsets[NSEG] = N_EDGES;
}
__global__ void k_scatter(const int* __restrict__ ei, const int* __restrict__ et) {
    int e = blockIdx.x * blockDim.x + threadIdx.x;
    if (e < N_EDGES) {
        int dst = ei[N_EDGES + e];
        int r = et[e];
        int pos = atomicAdd(&g_cursor[dst * NREL + r], 1);
        g_rowid[pos] = (ei[e] << 4) | r;
    }
}

// ---------------- build W^T (K-major, fp16), root appended as relation 9 ----------------
__global__ void k_buildW1t(const float* __restrict__ bases, const float* __restrict__ comp,
                           const float* __restrict__ root) {
    int idx = blockIdx.x * blockDim.x + threadIdx.x;
    if (idx >= W1_COLS * IN_DIM) return;
    int col = idx / IN_DIM, k = idx % IN_DIM;
    int r = col / HID_DIM, o = col % HID_DIM;
    float v;
    if (r == NREL) v = root[k * HID_DIM + o];
    else {
        v = 0.f;
#pragma unroll
        for (int b = 0; b < NB; b++)
            v += comp[r * NB + b] * bases[((size_t)b * IN_DIM + k) * HID_DIM + o];
    }
    g_W1t[idx] = __float2half(v);
}
__global__ void k_buildW2t(const float* __restrict__ bases, const float* __restrict__ comp,
                           const float* __restrict__ root) {
    int idx = blockIdx.x * blockDim.x + threadIdx.x;
    if (idx >= W2_COLS * HID_DIM) return;
    int col = idx / HID_DIM, k = idx % HID_DIM;
    int r = col / OUT_DIM, o = col % OUT_DIM;
    float v;
    if (r == NREL) v = root[k * OUT_DIM + o];
    else {
        v = 0.f;
#pragma unroll
        for (int b = 0; b < NB; b++)
            v += comp[r * NB + b] * bases[((size_t)b * HID_DIM + k) * OUT_DIM + o];
    }
    g_W2t[idx] = __float2half(v);
}

// ---------------- GEMM: C[MPAD,N](fp16) = A[MPAD,K](fp16) @ Bt[N,K]^T(fp16) ----------------
// 256 threads, CTA tile 128x128; col0 = column-block offset (in 128-col units).
__global__ void __launch_bounds__(256)
k_tc_gemm(const __half* __restrict__ A, const __half* __restrict__ Bt,
          __half* __restrict__ C, int Ktot, int N, int col0) {
#if HAS_TCGEN05
    extern __shared__ char smem[];
    const uint32_t sb = smem_u32(smem);
    char* sA = smem + 1024;
    char* sB = smem + 1024 + 32768;
    int tid = threadIdx.x, wid = tid >> 5, lid = tid & 31;
    int rowBase = blockIdx.y * 128, colBase = (blockIdx.x + col0) * 128;

    if (wid == 0) { tmem_alloc(sb, 128); tmem_relinquish(); }
    if (tid == 0) mbar_init(sb + 8, 1);
    __syncthreads();
    uint32_t tmem;
    asm volatile("ld.shared.b32 %0, [%1];" : "=r"(tmem) : "r"(sb));

    const uint32_t idesc = 0x8200010u;
    const uint64_t da = make_desc(sb + 1024);
    const uint64_t db = make_desc(sb + 1024 + 32768);

    int nKc = Ktot >> 7;
    for (int kc = 0; kc < nKc; kc++) {
        if (kc > 0) mbar_wait(sb + 8, (kc - 1) & 1);
        int k0 = kc << 7;
#pragma unroll
        for (int i = 0; i < 8; i++) {
            int fid = i * 256 + tid;
            int r = fid >> 4;
            int c = (fid & 15) * 8;
            uint4 va = *(const uint4*)(A + (size_t)(rowBase + r) * Ktot + k0 + c);
            sts_h8(sA, r, c, va);
            uint4 vb = *(const uint4*)(Bt + (size_t)(colBase + r) * Ktot + k0 + c);
            sts_h8(sB, r, c, vb);
        }
        asm volatile("fence.proxy.async.shared::cta;" ::: "memory");
        __syncthreads();
        if (wid == 0) {
            if (elect_one()) {
#pragma unroll
                for (int ks = 0; ks < 8; ks++) {
                    uint64_t off = (uint64_t)((ks >> 2) * 1024 + (ks & 3) * 2);
                    mma_f16_ss(tmem, da + off, db + off, idesc, (kc | ks) != 0);
                }
                tc_commit(sb + 8);
            }
        }
    }
    mbar_wait(sb + 8, (nKc - 1) & 1);
    asm volatile("tcgen05.fence::after_thread_sync;" ::: "memory");

    float* stg = (float*)(smem + 1024) + wid * (32 * 33);
    int rowOff = (wid & 3) * 32;
    int colOff = (wid >> 2) * 64;
    for (int cb = 0; cb < 64; cb += 32) {
        uint32_t rg[32];
        LDTM_X32(rg, tmem + colOff + cb);
        asm volatile("tcgen05.wait::ld.sync.aligned;" ::: "memory");
#pragma unroll
        for (int j = 0; j < 32; j++) stg[lid * 33 + j] = __uint_as_float(rg[j]);
        __syncwarp();
        __half* crow = C + (size_t)(rowBase + rowOff) * N + colBase + colOff + cb;
#pragma unroll 4
        for (int rr = 0; rr < 32; rr++)
            crow[(size_t)rr * N + lid] = __float2half(stg[rr * 33 + lid]);
        __syncwarp();
    }
    asm volatile("tcgen05.fence::before_thread_sync;" ::: "memory");
    __syncthreads();
    if (wid == 0) tmem_dealloc(tmem, 128);
#else
    // ---- SIMT fallback (non-sm_103a passes), correctness only ----
    extern __shared__ char smem[];
    float* As = (float*)smem;
    float* Bs = (float*)smem + 8 * 128;
    int tid = threadIdx.x;
    int rowBase = blockIdx.y * 128, colBase = (blockIdx.x + col0) * 128;
    int tr = (tid >> 4) * 8;
    int tc = (tid & 15) * 8;

    float acc[8][8] = {};
    for (int k0 = 0; k0 < Ktot; k0 += 8) {
        if (tid < 128) {
            uint4 av = *(const uint4*)(A + (size_t)(rowBase + tid) * Ktot + k0);
            const __half2* ah = (const __half2*)&av;
#pragma unroll
            for (int j = 0; j < 4; j++) {
                float2 f = __half22float2(ah[j]);
                As[(2 * j) * 128 + tid] = f.x;
                As[(2 * j + 1) * 128 + tid] = f.y;
            }
        } else {
            int t2 = tid - 128;
            uint4 bv = *(const uint4*)(Bt + (size_t)(colBase + t2) * Ktot + k0);
            const __half2* bh = (const __half2*)&bv;
#pragma unroll
            for (int j = 0; j < 4; j++) {
                float2 f = __half22float2(bh[j]);
                Bs[(2 * j) * 128 + t2] = f.x;
                Bs[(2 * j + 1) * 128 + t2] = f.y;
            }
        }
        __syncthreads();
#pragma unroll
        for (int kk = 0; kk < 8; kk++) {
            float rm[8], rn[8];
#pragma unroll
            for (int i = 0; i < 8; i++) rm[i] = As[kk * 128 + tr + i];
#pragma unroll
            for (int j = 0; j < 8; j++) rn[j] = Bs[kk * 128 + tc + j];
#pragma unroll
            for (int i = 0; i < 8; i++)
#pragma unroll
                for (int j = 0; j < 8; j++) acc[i][j] += rm[i] * rn[j];
        }
        __syncthreads();
    }
#pragma unroll
    for (int i = 0; i < 8; i++) {
        int row = rowBase + tr + i;
#pragma unroll
        for (int j = 0; j < 8; j++)
            C[(size_t)row * N + colBase + tc + j] = __float2half(acc[i][j]);
    }
#endif
}

// ---------------- per-relation max update: acc[n] = max(acc[n], max_{edges(n,r)} Y1slice) ----------------
__global__ void __launch_bounds__(128) k_aggmax_rel(int r) {
    int n = blockIdx.x;
    int t = threadIdx.x;
    int s0 = g_offsets[n * NREL + r];
    int s1 = g_offsets[n * NREL + r + 1];
    int deg = s1 - s0;
    if (deg == 0) return;

    const __half2* Y = (const __half2*)g_Y1;
    int cb = r * (HID_DIM / 2) + t;                 // column (half2) within row
    float mx = -INFINITY, my = -INFINITY;
    int i = 0;
    for (; i + 4 <= deg; i += 4) {
        int r0 = g_rowid[s0 + i + 0] >> 4;
        int r1 = g_rowid[s0 + i + 1] >> 4;
        int r2 = g_rowid[s0 + i + 2] >> 4;
        int r3 = g_rowid[s0 + i + 3] >> 4;
        float2 f0 = __half22float2(Y[(size_t)r0 * (W1_COLS / 2) + cb]);
        float2 f1 = __half22float2(Y[(size_t)r1 * (W1_COLS / 2) + cb]);
        float2 f2 = __half22float2(Y[(size_t)r2 * (W1_COLS / 2) + cb]);
        float2 f3 = __half22float2(Y[(size_t)r3 * (W1_COLS / 2) + cb]);
        mx = fmaxf(fmaxf(fmaxf(mx, f0.x), fmaxf(f1.x, f2.x)), f3.x);
        my = fmaxf(fmaxf(fmaxf(my, f0.y), fmaxf(f1.y, f2.y)), f3.y);
    }
    for (; i < deg; i++) {
        int row = g_rowid[s0 + i] >> 4;
        float2 f = __half22float2(Y[(size_t)row * (W1_COLS / 2) + cb]);
        mx = fmaxf(mx, f.x);
        my = fmaxf(my, f.y);
    }
    float2* A2 = (float2*)g_acc + (size_t)n * (HID_DIM / 2) + t;
    float2 a = *A2;
    a.x = fmaxf(a.x, mx);
    a.y = fmaxf(a.y, my);
    *A2 = a;
}

// ---------------- finalize layer 1: isfinite fixup + root + bias + LN + ReLU -> fp16 h ----------------
__global__ void __launch_bounds__(128) k_fin1(const float* __restrict__ bias,
                                              const float* __restrict__ gamma,
                                              const float* __restrict__ beta) {
    int n = blockIdx.x;
    int t = threadIdx.x;
    if (n >= N_NODES) {
        ((__half2*)g_h)[(size_t)n * (HID_DIM / 2) + t] = __half2(__half(0.f), __half(0.f));
        return;
    }
    float2 a = ((const float2*)g_acc)[(size_t)n * (HID_DIM / 2) + t];
    float mx = isfinite(a.x) ? a.x : 0.f;
    float my = isfinite(a.y) ? a.y : 0.f;

    const __half2* Y = (const __half2*)g_Y1;
    float2 rootv = __half22float2(Y[(size_t)n * (W1_COLS / 2) + NREL * (HID_DIM / 2) + t]);
    float2 bi = ((const float2*)bias)[t];
    float vx = mx + rootv.x + bi.x;
    float vy = my + rootv.y + bi.y;

    float s = vx + vy, s2 = vx * vx + vy * vy;
#pragma unroll
    for (int o = 16; o > 0; o >>= 1) {
        s  += __shfl_xor_sync(0xffffffffu, s, o);
        s2 += __shfl_xor_sync(0xffffffffu, s2, o);
    }
    __shared__ float ws[4], ws2[4];
    int w = t >> 5, l = t & 31;
    if (l == 0) { ws[w] = s; ws2[w] = s2; }
    __syncthreads();
    float ts = ws[0] + ws[1] + ws[2] + ws[3];
    float ts2 = ws2[0] + ws2[1] + ws2[2] + ws2[3];
    float mean = ts * (1.f / HID_DIM);
    float var  = ts2 * (1.f / HID_DIM) - mean * mean;
    float rstd = rsqrtf(var + LN_EPS);
    float2 ga = ((const float2*)gamma)[t];
    float2 be = ((const float2*)beta)[t];
    float yx = (vx - mean) * rstd * ga.x + be.x;
    float yy = (vy - mean) * rstd * ga.y + be.y;
    ((__half2*)g_h)[(size_t)n * (HID_DIM / 2) + t] =
        __floats2half2_rn(fmaxf(yx, 0.f), fmaxf(yy, 0.f));
}

// ---------------- layer 2: gather-sum + root + bias + LN + log_softmax ----------------
__global__ void __launch_bounds__(256) k_agg2(const float* __restrict__ bias,
                                              const float* __restrict__ gamma,
                                              const float* __restrict__ beta,
                                              float* __restrict__ out) {
    int n = blockIdx.x * 8 + (threadIdx.x >> 5);
    if (n >= N_NODES) return;
    int lane = threadIdx.x & 31;
    int start = g_offsets[n * NREL];
    int end   = g_offsets[(n + 1) * NREL];
    int deg = end - start;
    const __half2* Y = (const __half2*)g_Y2;

    float sx = 0.f, sy = 0.f;
    int i = 0;
    for (; i + 4 <= deg; i += 4) {
        int p0 = g_rowid[start + i + 0];
        int p1 = g_rowid[start + i + 1];
        int p2 = g_rowid[start + i + 2];
        int p3 = g_rowid[start + i + 3];
        float2 f0 = __half22float2(Y[(size_t)(p0 >> 4) * (W2_COLS / 2) + (p0 & 15) * (OUT_DIM / 2) + lane]);
        float2 f1 = __half22float2(Y[(size_t)(p1 >> 4) * (W2_COLS / 2) + (p1 & 15) * (OUT_DIM / 2) + lane]);
        float2 f2 = __half22float2(Y[(size_t)(p2 >> 4) * (W2_COLS / 2) + (p2 & 15) * (OUT_DIM / 2) + lane]);
        float2 f3 = __half22float2(Y[(size_t)(p3 >> 4) * (W2_COLS / 2) + (p3 & 15) * (OUT_DIM / 2) + lane]);
        sx += (f0.x + f1.x) + (f2.x + f3.x);
        sy += (f0.y + f1.y) + (f2.y + f3.y);
    }
    for (; i < deg; i++) {
        int p = g_rowid[start + i];
        float2 f = __half22float2(Y[(size_t)(p >> 4) * (W2_COLS / 2) + (p & 15) * (OUT_DIM / 2) + lane]);
        sx += f.x; sy += f.y;
    }
    float2 rootv = __half22float2(Y[(size_t)n * (W2_COLS / 2) + NREL * (OUT_DIM / 2) + lane]);
    float2 bi = ((const float2*)bias)[lane];
    float vx = sx + rootv.x + bi.x;
    float vy = sy + rootv.y + bi.y;

    float a = vx + vy, b = vx * vx + vy * vy;
#pragma unroll
    for (int o = 16; o > 0; o >>= 1) {
        a += __shfl_xor_sync(0xffffffffu, a, o);
        b += __shfl_xor_sync(0xffffffffu, b, o);
    }
    float mean = a * (1.f / OUT_DIM);
    float var  = b * (1.f / OUT_DIM) - mean * mean;
    float rstd = rsqrtf(var + LN_EPS);
    float2 ga = ((const float2*)gamma)[lane];
    float2 be = ((const float2*)beta)[lane];
    float yx = (vx - mean) * rstd * ga.x + be.x;
    float yy = (vy - mean) * rstd * ga.y + be.y;

    float mx = fmaxf(yx, yy);
#pragma unroll
    for (int o = 16; o > 0; o >>= 1) mx = fmaxf(mx, __shfl_xor_sync(0xffffffffu, mx, o));
    float es = expf(yx - mx) + expf(yy - mx);
#pragma unroll
    for (int o = 16; o > 0; o >>= 1) es += __shfl_xor_sync(0xffffffffu, es, o);
    float lse = mx + logf(es);

    ((float2*)out)[(size_t)n * (OUT_DIM / 2) + lane] = make_float2(yx - lse, yy - lse);
}

// ---------------- host launch ----------------
extern "C" void kernel_launch(void* const* d_in, const int* in_sizes, int n_in,
                              void* d_out, int out_size) {
    const float* x      = (const float*)d_in[0];
    const int*   ei     = (const int*)d_in[1];
    const int*   et     = (const int*)d_in[2];
    const float* bases1 = (const float*)d_in[3];
    const float* comp1  = (const float*)d_in[4];
    const float* root1  = (const float*)d_in[5];
    const float* bias1  = (const float*)d_in[6];
    const float* g1     = (const float*)d_in[7];
    const float* b1     = (const float*)d_in[8];
    const float* bases2 = (const float*)d_in[9];
    const float* comp2  = (const float*)d_in[10];
    const float* root2  = (const float*)d_in[11];
    const float* bias2  = (const float*)d_in[12];
    const float* g2     = (const float*)d_in[13];
    const float* b2     = (const float*)d_in[14];
    float* out = (float*)d_out;

    __half *pxh, *pW1t, *pW2t, *pY1, *pY2, *ph;
    cudaGetSymbolAddress((void**)&pxh,  g_xh);
    cudaGetSymbolAddress((void**)&pW1t, g_W1t);
    cudaGetSymbolAddress((void**)&pW2t, g_W2t);
    cudaGetSymbolAddress((void**)&pY1,  g_Y1);
    cudaGetSymbolAddress((void**)&pY2,  g_Y2);
    cudaGetSymbolAddress((void**)&ph,   g_h);

    const int SMEM_GEMM = 1024 + 2 * 32768;   // 66560 B
    cudaFuncSetAttribute(k_tc_gemm, cudaFuncAttributeMaxDynamicSharedMemorySize, SMEM_GEMM);

    // lazy one-time stream/event creation (identical work every call)
    static cudaStream_t s2 = nullptr;
    static cudaEvent_t evFork = nullptr, evJoin = nullptr, evG[NREL];
    if (s2 == nullptr) {
        cudaStreamCreateWithFlags(&s2, cudaStreamNonBlocking);
        cudaEventCreateWithFlags(&evFork, cudaEventDisableTiming);
        cudaEventCreateWithFlags(&evJoin, cudaEventDisableTiming);
        for (int r = 0; r < NREL; r++)
            cudaEventCreateWithFlags(&evG[r], cudaEventDisableTiming);
    }

    // fork
    cudaEventRecord(evFork, 0);
    cudaStreamWaitEvent(s2, evFork, 0);

    // --- side stream: acc init + CSR build + W2 ---
    k_init_acc<<<(N_NODES * HID_DIM / 4 + 255) / 256, 256, 0, s2>>>();
    k_zero_counts<<<(NSEG + 255) / 256, 256, 0, s2>>>();
    k_count<<<(N_EDGES + 255) / 256, 256, 0, s2>>>(ei, et);
    k_scan1<<<SCAN1_BLOCKS, 256, 0, s2>>>();
    k_scan2<<<1, 1024, 0, s2>>>();
    k_scan3<<<SCAN1_BLOCKS, 256, 0, s2>>>();
    k_scatter<<<(N_EDGES + 255) / 256, 256, 0, s2>>>(ei, et);
    k_buildW2t<<<(W2_COLS * HID_DIM + 255) / 256, 256, 0, s2>>>(bases2, comp2, root2);

    // --- main stream: x->fp16, W1 ---
    k_x2h<<<(MPAD * IN_DIM / 4 + 255) / 256, 256>>>(x);
    k_buildW1t<<<(W1_COLS * IN_DIM + 255) / 256, 256>>>(bases1, comp1, root1);

    // layer 1 GEMM per relation (col blocks of 256 = 2x128), overlapped max-agg on s2
    for (int r = 0; r < NREL; r++) {
        dim3 grid(2, MPAD / 128);
        k_tc_gemm<<<grid, 256, SMEM_GEMM>>>(pxh, pW1t, pY1, IN_DIM, W1_COLS, r * 2);
        cudaEventRecord(evG[r], 0);
        cudaStreamWaitEvent(s2, evG[r], 0);
        k_aggmax_rel<<<N_NODES, 128, 0, s2>>>(r);
    }
    // root slice (relation 9) on main stream
    {
        dim3 grid(2, MPAD / 128);
        k_tc_gemm<<<grid, 256, SMEM_GEMM>>>(pxh, pW1t, pY1, IN_DIM, W1_COLS, NREL * 2);
    }
    cudaEventRecord(evJoin, s2);
    cudaStreamWaitEvent(0, evJoin, 0);

    // finalize layer 1
    k_fin1<<<MPAD, 128>>>(bias1, g1, b1);

    // layer 2: Y2 = h @ W2cat   (M=20096, N=640, K=256)
    {
        dim3 grid(W2_COLS / 128, MPAD / 128);
        k_tc_gemm<<<grid, 256, SMEM_GEMM>>>(ph, pW2t, pY2, HID_DIM, W2_COLS, 0);
    }
    k_agg2<<<(N_NODES + 7) / 8, 256>>>(bias2, g2, b2, out);
}

// round 11
// speedup vs baseline: 1.4803x; 1.4803x over previous
#include <cuda_runtime.h>
#include <cuda_fp16.h>
#include <math.h>
#include <stdint.h>

#define N_NODES 20000
#define MPAD    20096            // 157 * 128
#define N_EDGES 320000
#define NREL 9
#define NB 9
#define IN_DIM 128
#define HID_DIM 256
#define OUT_DIM 64
#define W1_COLS ((NREL + 1) * HID_DIM)   // 2560
#define W2_COLS ((NREL + 1) * OUT_DIM)   // 640
#define LN_EPS 1e-5f
#define SCAN_BLOCKS 80                   // 80 * 256 = 20480 >= N_NODES

// ---------------- static device scratch ----------------
__device__ __half g_xh[(size_t)MPAD * IN_DIM];            // x in fp16, padded
__device__ __half g_W1t[W1_COLS * IN_DIM];                // [2560,128] K-major fp16
__device__ __half g_W2t[W2_COLS * HID_DIM];               // [640,256]  K-major fp16
__device__ __half g_Y1[(size_t)MPAD * W1_COLS];           // ~103 MB
__device__ __half g_Y2[(size_t)MPAD * W2_COLS];           // ~26 MB
__device__ __half g_h[(size_t)MPAD * HID_DIM];            // ~10 MB fp16
__device__ int    g_counts[N_NODES];
__device__ int    g_offsets[N_NODES];
__device__ int    g_cursor[N_NODES];
__device__ int    g_rowid[N_EDGES];
__device__ int    g_blocksum[SCAN_BLOCKS];

// ---------------- helpers ----------------
static __device__ __forceinline__ uint32_t smem_u32(const void* p) {
    uint32_t a;
    asm("{ .reg .u64 t; cvta.to.shared.u64 t, %1; cvt.u32.u64 %0, t; }" : "=r"(a) : "l"(p));
    return a;
}

#if defined(__CUDA_ARCH__) && defined(__CUDA_ARCH_FEAT_SM103_ALL)
#define HAS_TCGEN05 1
#else
#define HAS_TCGEN05 0
#endif

#if HAS_TCGEN05
static __device__ __forceinline__ uint32_t elect_one() {
    uint32_t p;
    asm volatile("{\n\t.reg .pred p;\n\telect.sync _|p, 0xFFFFFFFF;\n\tselp.b32 %0, 1, 0, p;\n\t}" : "=r"(p));
    return p;
}
static __device__ __forceinline__ void mbar_init(uint32_t a, uint32_t cnt) {
    asm volatile("mbarrier.init.shared.b64 [%0], %1;" :: "r"(a), "r"(cnt) : "memory");
}
static __device__ __forceinline__ void mbar_wait(uint32_t a, uint32_t parity) {
    asm volatile(
        "{\n\t.reg .pred P;\n\t"
        "WL_%=:\n\t"
        "mbarrier.try_wait.parity.acquire.cta.shared::cta.b64 P, [%0], %1, 0x989680;\n\t"
        "@P bra WD_%=;\n\t"
        "bra WL_%=;\n\t"
        "WD_%=:\n\t}"
        :: "r"(a), "r"(parity) : "memory");
}
static __device__ __forceinline__ void tmem_alloc(uint32_t dst_smem, uint32_t ncols) {
    asm volatile("tcgen05.alloc.cta_group::1.sync.aligned.shared::cta.b32 [%0], %1;"
                 :: "r"(dst_smem), "r"(ncols) : "memory");
}
static __device__ __forceinline__ void tmem_dealloc(uint32_t tmem, uint32_t ncols) {
    asm volatile("tcgen05.dealloc.cta_group::1.sync.aligned.b32 %0, %1;" :: "r"(tmem), "r"(ncols));
}
static __device__ __forceinline__ void tmem_relinquish() {
    asm volatile("tcgen05.relinquish_alloc_permit.cta_group::1.sync.aligned;");
}
static __device__ __forceinline__ void tc_commit(uint32_t mbar) {
    asm volatile("tcgen05.commit.cta_group::1.mbarrier::arrive::one.shared::cluster.b64 [%0];"
                 :: "r"(mbar) : "memory");
}
static __device__ __forceinline__ void mma_f16_ss(uint32_t d, uint64_t adesc, uint64_t bdesc,
                                                  uint32_t idesc, uint32_t en) {
    asm volatile(
        "{\n\t.reg .pred p;\n\t"
        "setp.ne.u32 p, %5, 0;\n\t"
        "tcgen05.mma.cta_group::1.kind::f16 [%0], %1, %2, %3, {%4, %4, %4, %4}, p;\n\t}"
        :: "r"(d), "l"(adesc), "l"(bdesc), "r"(idesc), "r"(0u), "r"(en)
        : "memory");
}
// SW128 K-major SMEM descriptor: layout=SW128(2), version=1, SBO=64, LBO=1
static __device__ __forceinline__ uint64_t make_desc(uint32_t smem_addr) {
    const uint64_t base = (uint64_t(2) << 61) | (uint64_t(1) << 46) | (uint64_t(64) << 32) | (uint64_t(1) << 16);
    return base | ((uint64_t)(smem_addr >> 4) & 0x3FFF);
}
// swizzled store of 8 fp16 (16B) at (row r, fp16-col c, c % 8 == 0) of a 128x128 fp16
// blocked-atom tile (atom = 8 rows x 64 fp16 = 1024B; atom idx = (r>>3) + (c>>6)*16)
static __device__ __forceinline__ void sts_h8(char* tile, int r, int c, uint4 v) {
    int off = ((r >> 3) + (c >> 6) * 16) * 1024 + (r & 7) * 128 + (c & 63) * 2;
    off ^= (off >> 3) & 0x70;
    *(uint4*)(tile + off) = v;
}

#define LDTM_X32(r, addr) \
    asm volatile( \
        "tcgen05.ld.sync.aligned.32x32b.x32.b32 " \
        "{%0, %1, %2, %3, %4, %5, %6, %7, " \
        " %8, %9, %10, %11, %12, %13, %14, %15, " \
        " %16, %17, %18, %19, %20, %21, %22, %23, " \
        " %24, %25, %26, %27, %28, %29, %30, %31}, [%32];" \
        : "=r"((r)[0]),  "=r"((r)[1]),  "=r"((r)[2]),  "=r"((r)[3]), \
          "=r"((r)[4]),  "=r"((r)[5]),  "=r"((r)[6]),  "=r"((r)[7]), \
          "=r"((r)[8]),  "=r"((r)[9]),  "=r"((r)[10]), "=r"((r)[11]), \
          "=r"((r)[12]), "=r"((r)[13]), "=r"((r)[14]), "=r"((r)[15]), \
          "=r"((r)[16]), "=r"((r)[17]), "=r"((r)[18]), "=r"((r)[19]), \
          "=r"((r)[20]), "=r"((r)[21]), "=r"((r)[22]), "=r"((r)[23]), \
          "=r"((r)[24]), "=r"((r)[25]), "=r"((r)[26]), "=r"((r)[27]), \
          "=r"((r)[28]), "=r"((r)[29]), "=r"((r)[30]), "=r"((r)[31]) \
        : "r"(addr))
#endif  // HAS_TCGEN05

// ---------------- x -> fp16 (padded to MPAD) ----------------
__global__ void k_x2h(const float* __restrict__ x) {
    int idx = blockIdx.x * blockDim.x + threadIdx.x;   // over MPAD*IN_DIM/4
    if (idx >= MPAD * IN_DIM / 4) return;
    int row = idx / (IN_DIM / 4);
    __half2 h0 = __half2(__float2half(0.f), __float2half(0.f)), h1 = h0;
    if (row < N_NODES) {
        float4 v = *(const float4*)(x + (size_t)idx * 4);
        h0 = __floats2half2_rn(v.x, v.y);
        h1 = __floats2half2_rn(v.z, v.w);
    }
    __half2* o = (__half2*)g_xh + (size_t)idx * 2;
    o[0] = h0; o[1] = h1;
}

// ---------------- CSR build ----------------
__global__ void k_zero_counts() {
    int i = blockIdx.x * blockDim.x + threadIdx.x;
    if (i < N_NODES) g_counts[i] = 0;
}
__global__ void k_count(const int* __restrict__ ei) {
    int e = blockIdx.x * blockDim.x + threadIdx.x;
    if (e < N_EDGES) atomicAdd(&g_counts[ei[N_EDGES + e]], 1);
}
// phase 1: block-local exclusive scan (256/block), block totals to g_blocksum
__global__ void __launch_bounds__(256) k_scan1() {
    int t = threadIdx.x, lane = t & 31, w = t >> 5;
    int i = blockIdx.x * 256 + t;
    int v = (i < N_NODES) ? g_counts[i] : 0;
    int x = v;
#pragma unroll
    for (int o = 1; o < 32; o <<= 1) {
        int y = __shfl_up_sync(0xffffffffu, x, o);
        if (lane >= o) x += y;
    }
    __shared__ int ws[8];
    if (lane == 31) ws[w] = x;
    __syncthreads();
    int add = 0;
#pragma unroll
    for (int k = 0; k < 8; k++) add += (k < w) ? ws[k] : 0;
    if (i < N_NODES) g_offsets[i] = x - v + add;           // exclusive, block-local
    if (t == 255) g_blocksum[blockIdx.x] = x + add;        // block total
}
// phase 2: exclusive scan of the 80 block sums (one tiny block)
__global__ void __launch_bounds__(128) k_scan2() {
    int t = threadIdx.x, lane = t & 31, w = t >> 5;
    int v = (t < SCAN_BLOCKS) ? g_blocksum[t] : 0;
    int x = v;
#pragma unroll
    for (int o = 1; o < 32; o <<= 1) {
        int y = __shfl_up_sync(0xffffffffu, x, o);
        if (lane >= o) x += y;
    }
    __shared__ int ws[4];
    if (lane == 31) ws[w] = x;
    __syncthreads();
    int add = 0;
#pragma unroll
    for (int k = 0; k < 4; k++) add += (k < w) ? ws[k] : 0;
    if (t < SCAN_BLOCKS) g_blocksum[t] = x - v + add;      // exclusive
}
// phase 3: add block offsets; materialize offsets + cursor
__global__ void __launch_bounds__(256) k_scan3() {
    int i = blockIdx.x * 256 + threadIdx.x;
    if (i < N_NODES) {
        int o = g_offsets[i] + g_blocksum[blockIdx.x];
        g_offsets[i] = o;
        g_cursor[i]  = o;
    }
}
__global__ void k_scatter(const int* __restrict__ ei, const int* __restrict__ et) {
    int e = blockIdx.x * blockDim.x + threadIdx.x;
    if (e < N_EDGES) {
        int dst = ei[N_EDGES + e];
        int pos = atomicAdd(&g_cursor[dst], 1);
        g_rowid[pos] = ei[e] * (NREL + 1) + et[e];
    }
}

// ---------------- build W^T (K-major, fp16), root appended as relation 9 ----------------
__global__ void k_buildW1t(const float* __restrict__ bases, const float* __restrict__ comp,
                           const float* __restrict__ root) {
    int idx = blockIdx.x * blockDim.x + threadIdx.x;
    if (idx >= W1_COLS * IN_DIM) return;
    int col = idx / IN_DIM, k = idx % IN_DIM;
    int r = col / HID_DIM, o = col % HID_DIM;
    float v;
    if (r == NREL) v = root[k * HID_DIM + o];
    else {
        v = 0.f;
#pragma unroll
        for (int b = 0; b < NB; b++)
            v += comp[r * NB + b] * bases[((size_t)b * IN_DIM + k) * HID_DIM + o];
    }
    g_W1t[idx] = __float2half(v);
}
__global__ void k_buildW2t(const float* __restrict__ bases, const float* __restrict__ comp,
                           const float* __restrict__ root) {
    int idx = blockIdx.x * blockDim.x + threadIdx.x;
    if (idx >= W2_COLS * HID_DIM) return;
    int col = idx / HID_DIM, k = idx % HID_DIM;
    int r = col / OUT_DIM, o = col % OUT_DIM;
    float v;
    if (r == NREL) v = root[k * OUT_DIM + o];
    else {
        v = 0.f;
#pragma unroll
        for (int b = 0; b < NB; b++)
            v += comp[r * NB + b] * bases[((size_t)b * HID_DIM + k) * OUT_DIM + o];
    }
    g_W2t[idx] = __float2half(v);
}

// ---------------- GEMM: C[MPAD,N](fp16) = A[MPAD,K](fp16) @ Bt[N,K]^T(fp16) ----------------
// 256 threads, CTA tile 128x128, K chunked by 128 (fp16 kind::f16 MMA, K=16/step).
__global__ void __launch_bounds__(256)
k_tc_gemm(const __half* __restrict__ A, const __half* __restrict__ Bt,
          __half* __restrict__ C, int Ktot, int N) {
#if HAS_TCGEN05
    extern __shared__ char smem[];
    const uint32_t sb = smem_u32(smem);
    char* sA = smem + 1024;
    char* sB = smem + 1024 + 32768;
    int tid = threadIdx.x, wid = tid >> 5, lid = tid & 31;
    int rowBase = blockIdx.y * 128, colBase = blockIdx.x * 128;

    if (wid == 0) { tmem_alloc(sb, 128); tmem_relinquish(); }
    if (tid == 0) mbar_init(sb + 8, 1);
    __syncthreads();
    uint32_t tmem;
    asm volatile("ld.shared.b32 %0, [%1];" : "=r"(tmem) : "r"(sb));

    // idesc: D=f32(1<<4), atype=f16(0), btype=f16(0), N/8=16(<<17), M/16=8(<<24)
    const uint32_t idesc = 0x8200010u;
    const uint64_t da = make_desc(sb + 1024);
    const uint64_t db = make_desc(sb + 1024 + 32768);

    int nKc = Ktot >> 7;                     // chunks of 128
    for (int kc = 0; kc < nKc; kc++) {
        if (kc > 0) mbar_wait(sb + 8, (kc - 1) & 1);
        int k0 = kc << 7;
#pragma unroll
        for (int i = 0; i < 8; i++) {
            int fid = i * 256 + tid;         // 2048 uint4 per tile
            int r = fid >> 4;                // 16 uint4 per 128-fp16 row
            int c = (fid & 15) * 8;
            uint4 va = *(const uint4*)(A + (size_t)(rowBase + r) * Ktot + k0 + c);
            sts_h8(sA, r, c, va);
            uint4 vb = *(const uint4*)(Bt + (size_t)(colBase + r) * Ktot + k0 + c);
            sts_h8(sB, r, c, vb);
        }
        asm volatile("fence.proxy.async.shared::cta;" ::: "memory");
        __syncthreads();
        if (wid == 0) {
            if (elect_one()) {
#pragma unroll
                for (int ks = 0; ks < 8; ks++) {   // K=16 per MMA
                    uint64_t off = (uint64_t)((ks >> 2) * 1024 + (ks & 3) * 2);
                    mma_f16_ss(tmem, da + off, db + off, idesc, (kc | ks) != 0);
                }
                tc_commit(sb + 8);
            }
        }
    }
    mbar_wait(sb + 8, (nKc - 1) & 1);
    asm volatile("tcgen05.fence::after_thread_sync;" ::: "memory");

    // epilogue: 8 warps; warp w -> rows (w&3)*32, col half (w>>2)*64
    float* stg = (float*)(smem + 1024) + wid * (32 * 33);
    int rowOff = (wid & 3) * 32;
    int colOff = (wid >> 2) * 64;
    for (int cb = 0; cb < 64; cb += 32) {
        uint32_t rg[32];
        LDTM_X32(rg, tmem + colOff + cb);
        asm volatile("tcgen05.wait::ld.sync.aligned;" ::: "memory");
#pragma unroll
        for (int j = 0; j < 32; j++) stg[lid * 33 + j] = __uint_as_float(rg[j]);
        __syncwarp();
        __half* crow = C + (size_t)(rowBase + rowOff) * N + colBase + colOff + cb;
#pragma unroll 4
        for (int rr = 0; rr < 32; rr++)
            crow[(size_t)rr * N + lid] = __float2half(stg[rr * 33 + lid]);
        __syncwarp();
    }
    asm volatile("tcgen05.fence::before_thread_sync;" ::: "memory");
    __syncthreads();
    if (wid == 0) tmem_dealloc(tmem, 128);
#else
    // ---- SIMT fallback (non-sm_103a passes), correctness only ----
    extern __shared__ char smem[];
    float* As = (float*)smem;              // [8][128]
    float* Bs = (float*)smem + 8 * 128;    // [8][128]
    int tid = threadIdx.x;
    int rowBase = blockIdx.y * 128, colBase = blockIdx.x * 128;
    int tr = (tid >> 4) * 8;               // 16 row groups of 8
    int tc = (tid & 15) * 8;               // 16 col groups of 8

    float acc[8][8] = {};
    for (int k0 = 0; k0 < Ktot; k0 += 8) {
        if (tid < 128) {
            uint4 av = *(const uint4*)(A + (size_t)(rowBase + tid) * Ktot + k0);
            const __half2* ah = (const __half2*)&av;
#pragma unroll
            for (int j = 0; j < 4; j++) {
                float2 f = __half22float2(ah[j]);
                As[(2 * j) * 128 + tid] = f.x;
                As[(2 * j + 1) * 128 + tid] = f.y;
            }
        } else {
            int t2 = tid - 128;
            uint4 bv = *(const uint4*)(Bt + (size_t)(colBase + t2) * Ktot + k0);
            const __half2* bh = (const __half2*)&bv;
#pragma unroll
            for (int j = 0; j < 4; j++) {
                float2 f = __half22float2(bh[j]);
                Bs[(2 * j) * 128 + t2] = f.x;
                Bs[(2 * j + 1) * 128 + t2] = f.y;
            }
        }
        __syncthreads();
#pragma unroll
        for (int kk = 0; kk < 8; kk++) {
            float rm[8], rn[8];
#pragma unroll
            for (int i = 0; i < 8; i++) rm[i] = As[kk * 128 + tr + i];
#pragma unroll
            for (int j = 0; j < 8; j++) rn[j] = Bs[kk * 128 + tc + j];
#pragma unroll
            for (int i = 0; i < 8; i++)
#pragma unroll
                for (int j = 0; j < 8; j++) acc[i][j] += rm[i] * rn[j];
        }
        __syncthreads();
    }
#pragma unroll
    for (int i = 0; i < 8; i++) {
        int row = rowBase + tr + i;
#pragma unroll
        for (int j = 0; j < 8; j++)
            C[(size_t)row * N + colBase + tc + j] = __float2half(acc[i][j]);
    }
#endif
}

// ---------------- layer 1: gather-max + root + bias + LN + ReLU -> fp16 h ----------------
__global__ void __launch_bounds__(128) k_agg1(const float* __restrict__ bias,
                                              const float* __restrict__ gamma,
                                              const float* __restrict__ beta) {
    int n = blockIdx.x;
    int t = threadIdx.x;
    if (n >= N_NODES) {   // zero pad rows so GEMM2 reads clean data
        ((__half2*)g_h)[(size_t)n * (HID_DIM / 2) + t] = __half2(__half(0.f), __half(0.f));
        return;
    }
    int start = g_offsets[n];
    int deg = g_counts[n];
    const __half2* Y = (const __half2*)g_Y1;

    float mx = -INFINITY, my = -INFINITY;
    int i = 0;
    for (; i + 4 <= deg; i += 4) {
        int r0 = g_rowid[start + i + 0];
        int r1 = g_rowid[start + i + 1];
        int r2 = g_rowid[start + i + 2];
        int r3 = g_rowid[start + i + 3];
        float2 f0 = __half22float2(Y[(size_t)r0 * (HID_DIM / 2) + t]);
        float2 f1 = __half22float2(Y[(size_t)r1 * (HID_DIM / 2) + t]);
        float2 f2 = __half22float2(Y[(size_t)r2 * (HID_DIM / 2) + t]);
        float2 f3 = __half22float2(Y[(size_t)r3 * (HID_DIM / 2) + t]);
        mx = fmaxf(fmaxf(fmaxf(mx, f0.x), fmaxf(f1.x, f2.x)), f3.x);
        my = fmaxf(fmaxf(fmaxf(my, f0.y), fmaxf(f1.y, f2.y)), f3.y);
    }
    for (; i < deg; i++) {
        int row = g_rowid[start + i];
        float2 f = __half22float2(Y[(size_t)row * (HID_DIM / 2) + t]);
        mx = fmaxf(mx, f.x);
        my = fmaxf(my, f.y);
    }
    if (deg == 0) { mx = 0.f; my = 0.f; }

    float2 rootv = __half22float2(Y[((size_t)n * W1_COLS + NREL * HID_DIM) / 2 + t]);
    float2 bi = ((const float2*)bias)[t];
    float vx = mx + rootv.x + bi.x;
    float vy = my + rootv.y + bi.y;

    float s = vx + vy, s2 = vx * vx + vy * vy;
#pragma unroll
    for (int o = 16; o > 0; o >>= 1) {
        s  += __shfl_xor_sync(0xffffffffu, s, o);
        s2 += __shfl_xor_sync(0xffffffffu, s2, o);
    }
    __shared__ float ws[4], ws2[4];
    int w = t >> 5, l = t & 31;
    if (l == 0) { ws[w] = s; ws2[w] = s2; }
    __syncthreads();
    float ts = ws[0] + ws[1] + ws[2] + ws[3];
    float ts2 = ws2[0] + ws2[1] + ws2[2] + ws2[3];
    float mean = ts * (1.f / HID_DIM);
    float var  = ts2 * (1.f / HID_DIM) - mean * mean;
    float rstd = rsqrtf(var + LN_EPS);
    float2 ga = ((const float2*)gamma)[t];
    float2 be = ((const float2*)beta)[t];
    float yx = (vx - mean) * rstd * ga.x + be.x;
    float yy = (vy - mean) * rstd * ga.y + be.y;
    ((__half2*)g_h)[(size_t)n * (HID_DIM / 2) + t] =
        __floats2half2_rn(fmaxf(yx, 0.f), fmaxf(yy, 0.f));
}

// ---------------- layer 2: gather-sum + root + bias + LN + log_softmax ----------------
__global__ void __launch_bounds__(256) k_agg2(const float* __restrict__ bias,
                                              const float* __restrict__ gamma,
                                              const float* __restrict__ beta,
                                              float* __restrict__ out) {
    int n = blockIdx.x * 8 + (threadIdx.x >> 5);
    if (n >= N_NODES) return;
    int lane = threadIdx.x & 31;
    int start = g_offsets[n];
    int deg = g_counts[n];
    const __half2* Y = (const __half2*)g_Y2;

    float sx = 0.f, sy = 0.f;
    int i = 0;
    for (; i + 4 <= deg; i += 4) {
        int r0 = g_rowid[start + i + 0];
        int r1 = g_rowid[start + i + 1];
        int r2 = g_rowid[start + i + 2];
        int r3 = g_rowid[start + i + 3];
        float2 f0 = __half22float2(Y[(size_t)r0 * (OUT_DIM / 2) + lane]);
        float2 f1 = __half22float2(Y[(size_t)r1 * (OUT_DIM / 2) + lane]);
        float2 f2 = __half22float2(Y[(size_t)r2 * (OUT_DIM / 2) + lane]);
        float2 f3 = __half22float2(Y[(size_t)r3 * (OUT_DIM / 2) + lane]);
        sx += (f0.x + f1.x) + (f2.x + f3.x);
        sy += (f0.y + f1.y) + (f2.y + f3.y);
    }
    for (; i < deg; i++) {
        int row = g_rowid[start + i];
        float2 f = __half22float2(Y[(size_t)row * (OUT_DIM / 2) + lane]);
        sx += f.x; sy += f.y;
    }
    float2 rootv = __half22float2(Y[((size_t)n * W2_COLS + NREL * OUT_DIM) / 2 + lane]);
    float2 bi = ((const float2*)bias)[lane];
    float vx = sx + rootv.x + bi.x;
    float vy = sy + rootv.y + bi.y;

    float a = vx + vy, b = vx * vx + vy * vy;
#pragma unroll
    for (int o = 16; o > 0; o >>= 1) {
        a += __shfl_xor_sync(0xffffffffu, a, o);
        b += __shfl_xor_sync(0xffffffffu, b, o);
    }
    float mean = a * (1.f / OUT_DIM);
    float var  = b * (1.f / OUT_DIM) - mean * mean;
    float rstd = rsqrtf(var + LN_EPS);
    float2 ga = ((const float2*)gamma)[lane];
    float2 be = ((const float2*)beta)[lane];
    float yx = (vx - mean) * rstd * ga.x + be.x;
    float yy = (vy - mean) * rstd * ga.y + be.y;

    float mx = fmaxf(yx, yy);
#pragma unroll
    for (int o = 16; o > 0; o >>= 1) mx = fmaxf(mx, __shfl_xor_sync(0xffffffffu, mx, o));
    float es = expf(yx - mx) + expf(yy - mx);
#pragma unroll
    for (int o = 16; o > 0; o >>= 1) es += __shfl_xor_sync(0xffffffffu, es, o);
    float lse = mx + logf(es);

    ((float2*)out)[(size_t)n * (OUT_DIM / 2) + lane] = make_float2(yx - lse, yy - lse);
}

// ---------------- host launch ----------------
extern "C" void kernel_launch(void* const* d_in, const int* in_sizes, int n_in,
                              void* d_out, int out_size) {
    const float* x      = (const float*)d_in[0];
    const int*   ei     = (const int*)d_in[1];
    const int*   et     = (const int*)d_in[2];
    const float* bases1 = (const float*)d_in[3];
    const float* comp1  = (const float*)d_in[4];
    const float* root1  = (const float*)d_in[5];
    const float* bias1  = (const float*)d_in[6];
    const float* g1     = (const float*)d_in[7];
    const float* b1     = (const float*)d_in[8];
    const float* bases2 = (const float*)d_in[9];
    const float* comp2  = (const float*)d_in[10];
    const float* root2  = (const float*)d_in[11];
    const float* bias2  = (const float*)d_in[12];
    const float* g2     = (const float*)d_in[13];
    const float* b2     = (const float*)d_in[14];
    float* out = (float*)d_out;

    __half *pxh, *pW1t, *pW2t, *pY1, *pY2, *ph;
    cudaGetSymbolAddress((void**)&pxh,  g_xh);
    cudaGetSymbolAddress((void**)&pW1t, g_W1t);
    cudaGetSymbolAddress((void**)&pW2t, g_W2t);
    cudaGetSymbolAddress((void**)&pY1,  g_Y1);
    cudaGetSymbolAddress((void**)&pY2,  g_Y2);
    cudaGetSymbolAddress((void**)&ph,   g_h);

    const int SMEM_GEMM = 1024 + 2 * 32768;   // 66560 B
    cudaFuncSetAttribute(k_tc_gemm, cudaFuncAttributeMaxDynamicSharedMemorySize, SMEM_GEMM);

    // lazy one-time stream/event creation (identical work every call)
    static cudaStream_t s2 = nullptr;
    static cudaEvent_t evFork = nullptr, evJoin = nullptr;
    if (s2 == nullptr) {
        cudaStreamCreateWithFlags(&s2, cudaStreamNonBlocking);
        cudaEventCreateWithFlags(&evFork, cudaEventDisableTiming);
        cudaEventCreateWithFlags(&evJoin, cudaEventDisableTiming);
    }

    // fork: CSR chain on s2, GEMM1 chain on the launch (capture) stream
    cudaEventRecord(evFork, 0);
    cudaStreamWaitEvent(s2, evFork, 0);

    // --- side stream: CSR build + W2 ---
    k_zero_counts<<<(N_NODES + 255) / 256, 256, 0, s2>>>();
    k_count<<<(N_EDGES + 255) / 256, 256, 0, s2>>>(ei);
    k_scan1<<<SCAN_BLOCKS, 256, 0, s2>>>();
    k_scan2<<<1, 128, 0, s2>>>();
    k_scan3<<<SCAN_BLOCKS, 256, 0, s2>>>();
    k_scatter<<<(N_EDGES + 255) / 256, 256, 0, s2>>>(ei, et);
    k_buildW2t<<<(W2_COLS * HID_DIM + 255) / 256, 256, 0, s2>>>(bases2, comp2, root2);
    cudaEventRecord(evJoin, s2);

    // --- main stream: x->fp16, W1, GEMM1 ---
    k_x2h<<<(MPAD * IN_DIM / 4 + 255) / 256, 256>>>(x);
    k_buildW1t<<<(W1_COLS * IN_DIM + 255) / 256, 256>>>(bases1, comp1, root1);
    {
        dim3 grid(W1_COLS / 128, MPAD / 128);
        k_tc_gemm<<<grid, 256, SMEM_GEMM>>>(pxh, pW1t, pY1, IN_DIM, W1_COLS);
    }

    // join: agg1 needs CSR + Y1
    cudaStreamWaitEvent(0, evJoin, 0);
    k_agg1<<<MPAD, 128>>>(bias1, g1, b1);

    // layer 2: Y2 = h @ W2cat   (M=20096, N=640, K=256)
    {
        dim3 grid(W2_COLS / 128, MPAD / 128);
        k_tc_gemm<<<grid, 256, SMEM_GEMM>>>(ph, pW2t, pY2, HID_DIM, W2_COLS);
    }
    k_agg2<<<(N_NODES + 7) / 8, 256>>>(bias2, g2, b2, out);
}

// round 12
// speedup vs baseline: 1.5831x; 1.0694x over previous
#include <cuda_runtime.h>
#include <cuda_fp16.h>
#include <math.h>
#include <stdint.h>

#define N_NODES 20000
#define MPAD    20096            // 157 * 128
#define N_EDGES 320000
#define NREL 9
#define NB 9
#define IN_DIM 128
#define HID_DIM 256
#define OUT_DIM 64
#define W1_COLS ((NREL + 1) * HID_DIM)   // 2560
#define W2_COLS ((NREL + 1) * OUT_DIM)   // 640
#define LN_EPS 1e-5f
#define SCAN_BLOCKS 80                   // 80 * 256 = 20480 >= N_NODES
#define MCHUNK0 79                       // first chunk: 79*128 = 10112 rows
#define MCHUNK1 78                       // second chunk: 78*128 = 9984 rows

// ---------------- static device scratch ----------------
__device__ __half g_xh[(size_t)MPAD * IN_DIM];            // x in fp16, padded
__device__ __half g_W1t[W1_COLS * IN_DIM];                // [2560,128] K-major fp16
__device__ __half g_W2t[W2_COLS * HID_DIM];               // [640,256]  K-major fp16
__device__ __half g_Y1[(size_t)MPAD * W1_COLS];           // ~103 MB
__device__ __half g_Y2[(size_t)MPAD * W2_COLS];           // ~26 MB
__device__ __half g_h[(size_t)MPAD * HID_DIM];            // ~10 MB fp16
__device__ int    g_counts[N_NODES];
__device__ int    g_offsets[N_NODES];
__device__ int    g_cursor[N_NODES];
__device__ int    g_rowid[N_EDGES];
__device__ int    g_blocksum[SCAN_BLOCKS];

// ---------------- helpers ----------------
static __device__ __forceinline__ uint32_t smem_u32(const void* p) {
    uint32_t a;
    asm("{ .reg .u64 t; cvta.to.shared.u64 t, %1; cvt.u32.u64 %0, t; }" : "=r"(a) : "l"(p));
    return a;
}

#if defined(__CUDA_ARCH__) && defined(__CUDA_ARCH_FEAT_SM103_ALL)
#define HAS_TCGEN05 1
#else
#define HAS_TCGEN05 0
#endif

#if HAS_TCGEN05
static __device__ __forceinline__ uint32_t elect_one() {
    uint32_t p;
    asm volatile("{\n\t.reg .pred p;\n\telect.sync _|p, 0xFFFFFFFF;\n\tselp.b32 %0, 1, 0, p;\n\t}" : "=r"(p));
    return p;
}
static __device__ __forceinline__ void mbar_init(uint32_t a, uint32_t cnt) {
    asm volatile("mbarrier.init.shared.b64 [%0], %1;" :: "r"(a), "r"(cnt) : "memory");
}
static __device__ __forceinline__ void mbar_wait(uint32_t a, uint32_t parity) {
    asm volatile(
        "{\n\t.reg .pred P;\n\t"
        "WL_%=:\n\t"
        "mbarrier.try_wait.parity.acquire.cta.shared::cta.b64 P, [%0], %1, 0x989680;\n\t"
        "@P bra WD_%=;\n\t"
        "bra WL_%=;\n\t"
        "WD_%=:\n\t}"
        :: "r"(a), "r"(parity) : "memory");
}
static __device__ __forceinline__ void tmem_alloc(uint32_t dst_smem, uint32_t ncols) {
    asm volatile("tcgen05.alloc.cta_group::1.sync.aligned.shared::cta.b32 [%0], %1;"
                 :: "r"(dst_smem), "r"(ncols) : "memory");
}
static __device__ __forceinline__ void tmem_dealloc(uint32_t tmem, uint32_t ncols) {
    asm volatile("tcgen05.dealloc.cta_group::1.sync.aligned.b32 %0, %1;" :: "r"(tmem), "r"(ncols));
}
static __device__ __forceinline__ void tmem_relinquish() {
    asm volatile("tcgen05.relinquish_alloc_permit.cta_group::1.sync.aligned;");
}
static __device__ __forceinline__ void tc_commit(uint32_t mbar) {
    asm volatile("tcgen05.commit.cta_group::1.mbarrier::arrive::one.shared::cluster.b64 [%0];"
                 :: "r"(mbar) : "memory");
}
static __device__ __forceinline__ void mma_f16_ss(uint32_t d, uint64_t adesc, uint64_t bdesc,
                                                  uint32_t idesc, uint32_t en) {
    asm volatile(
        "{\n\t.reg .pred p;\n\t"
        "setp.ne.u32 p, %5, 0;\n\t"
        "tcgen05.mma.cta_group::1.kind::f16 [%0], %1, %2, %3, {%4, %4, %4, %4}, p;\n\t}"
        :: "r"(d), "l"(adesc), "l"(bdesc), "r"(idesc), "r"(0u), "r"(en)
        : "memory");
}
// SW128 K-major SMEM descriptor: layout=SW128(2), version=1, SBO=64, LBO=1
static __device__ __forceinline__ uint64_t make_desc(uint32_t smem_addr) {
    const uint64_t base = (uint64_t(2) << 61) | (uint64_t(1) << 46) | (uint64_t(64) << 32) | (uint64_t(1) << 16);
    return base | ((uint64_t)(smem_addr >> 4) & 0x3FFF);
}
// swizzled store of 8 fp16 (16B) at (row r, fp16-col c, c % 8 == 0) of a 128x128 fp16 tile
static __device__ __forceinline__ void sts_h8(char* tile, int r, int c, uint4 v) {
    int off = ((r >> 3) + (c >> 6) * 16) * 1024 + (r & 7) * 128 + (c & 63) * 2;
    off ^= (off >> 3) & 0x70;
    *(uint4*)(tile + off) = v;
}
static __device__ __forceinline__ uint32_t pack_h2(uint32_t a, uint32_t b) {
    __half2 h = __floats2half2_rn(__uint_as_float(a), __uint_as_float(b));
    return *(uint32_t*)&h;
}

#define LDTM_X32(r, addr) \
    asm volatile( \
        "tcgen05.ld.sync.aligned.32x32b.x32.b32 " \
        "{%0, %1, %2, %3, %4, %5, %6, %7, " \
        " %8, %9, %10, %11, %12, %13, %14, %15, " \
        " %16, %17, %18, %19, %20, %21, %22, %23, " \
        " %24, %25, %26, %27, %28, %29, %30, %31}, [%32];" \
        : "=r"((r)[0]),  "=r"((r)[1]),  "=r"((r)[2]),  "=r"((r)[3]), \
          "=r"((r)[4]),  "=r"((r)[5]),  "=r"((r)[6]),  "=r"((r)[7]), \
          "=r"((r)[8]),  "=r"((r)[9]),  "=r"((r)[10]), "=r"((r)[11]), \
          "=r"((r)[12]), "=r"((r)[13]), "=r"((r)[14]), "=r"((r)[15]), \
          "=r"((r)[16]), "=r"((r)[17]), "=r"((r)[18]), "=r"((r)[19]), \
          "=r"((r)[20]), "=r"((r)[21]), "=r"((r)[22]), "=r"((r)[23]), \
          "=r"((r)[24]), "=r"((r)[25]), "=r"((r)[26]), "=r"((r)[27]), \
          "=r"((r)[28]), "=r"((r)[29]), "=r"((r)[30]), "=r"((r)[31]) \
        : "r"(addr))
#endif  // HAS_TCGEN05

// ---------------- fused prep: x -> fp16 (padded) + build W1^T ----------------
#define X2H_BLOCKS ((MPAD * IN_DIM / 4 + 255) / 256)
#define BW1_BLOCKS ((W1_COLS * IN_DIM + 255) / 256)
__global__ void k_prep1(const float* __restrict__ x, const float* __restrict__ bases,
                        const float* __restrict__ comp, const float* __restrict__ root) {
    if (blockIdx.x < X2H_BLOCKS) {
        int idx = blockIdx.x * 256 + threadIdx.x;
        if (idx >= MPAD * IN_DIM / 4) return;
        int row = idx / (IN_DIM / 4);
        __half2 h0 = __half2(__float2half(0.f), __float2half(0.f)), h1 = h0;
        if (row < N_NODES) {
            float4 v = *(const float4*)(x + (size_t)idx * 4);
            h0 = __floats2half2_rn(v.x, v.y);
            h1 = __floats2half2_rn(v.z, v.w);
        }
        __half2* o = (__half2*)g_xh + (size_t)idx * 2;
        o[0] = h0; o[1] = h1;
    } else {
        int idx = (blockIdx.x - X2H_BLOCKS) * 256 + threadIdx.x;
        if (idx >= W1_COLS * IN_DIM) return;
        int col = idx / IN_DIM, k = idx % IN_DIM;
        int r = col / HID_DIM, o = col % HID_DIM;
        float v;
        if (r == NREL) v = root[k * HID_DIM + o];
        else {
            v = 0.f;
#pragma unroll
            for (int b = 0; b < NB; b++)
                v += comp[r * NB + b] * bases[((size_t)b * IN_DIM + k) * HID_DIM + o];
        }
        g_W1t[idx] = __float2half(v);
    }
}

// ---------------- CSR build ----------------
__global__ void k_zero_counts() {
    int i = blockIdx.x * blockDim.x + threadIdx.x;
    if (i < N_NODES) g_counts[i] = 0;
}
__global__ void k_count(const int* __restrict__ ei) {
    int e = blockIdx.x * blockDim.x + threadIdx.x;
    if (e < N_EDGES) atomicAdd(&g_counts[ei[N_EDGES + e]], 1);
}
__global__ void __launch_bounds__(256) k_scan1() {
    int t = threadIdx.x, lane = t & 31, w = t >> 5;
    int i = blockIdx.x * 256 + t;
    int v = (i < N_NODES) ? g_counts[i] : 0;
    int x = v;
#pragma unroll
    for (int o = 1; o < 32; o <<= 1) {
        int y = __shfl_up_sync(0xffffffffu, x, o);
        if (lane >= o) x += y;
    }
    __shared__ int ws[8];
    if (lane == 31) ws[w] = x;
    __syncthreads();
    int add = 0;
#pragma unroll
    for (int k = 0; k < 8; k++) add += (k < w) ? ws[k] : 0;
    if (i < N_NODES) g_offsets[i] = x - v + add;
    if (t == 255) g_blocksum[blockIdx.x] = x + add;
}
__global__ void __launch_bounds__(128) k_scan2() {
    int t = threadIdx.x, lane = t & 31, w = t >> 5;
    int v = (t < SCAN_BLOCKS) ? g_blocksum[t] : 0;
    int x = v;
#pragma unroll
    for (int o = 1; o < 32; o <<= 1) {
        int y = __shfl_up_sync(0xffffffffu, x, o);
        if (lane >= o) x += y;
    }
    __shared__ int ws[4];
    if (lane == 31) ws[w] = x;
    __syncthreads();
    int add = 0;
#pragma unroll
    for (int k = 0; k < 4; k++) add += (k < w) ? ws[k] : 0;
    if (t < SCAN_BLOCKS) g_blocksum[t] = x - v + add;
}
__global__ void __launch_bounds__(256) k_scan3() {
    int i = blockIdx.x * 256 + threadIdx.x;
    if (i < N_NODES) {
        int o = g_offsets[i] + g_blocksum[blockIdx.x];
        g_offsets[i] = o;
        g_cursor[i]  = o;
    }
}
__global__ void k_scatter(const int* __restrict__ ei, const int* __restrict__ et) {
    int e = blockIdx.x * blockDim.x + threadIdx.x;
    if (e < N_EDGES) {
        int dst = ei[N_EDGES + e];
        int pos = atomicAdd(&g_cursor[dst], 1);
        g_rowid[pos] = ei[e] * (NREL + 1) + et[e];
    }
}

// ---------------- build W2^T (K-major, fp16) ----------------
__global__ void k_buildW2t(const float* __restrict__ bases, const float* __restrict__ comp,
                           const float* __restrict__ root) {
    int idx = blockIdx.x * blockDim.x + threadIdx.x;
    if (idx >= W2_COLS * HID_DIM) return;
    int col = idx / HID_DIM, k = idx % HID_DIM;
    int r = col / OUT_DIM, o = col % OUT_DIM;
    float v;
    if (r == NREL) v = root[k * OUT_DIM + o];
    else {
        v = 0.f;
#pragma unroll
        for (int b = 0; b < NB; b++)
            v += comp[r * NB + b] * bases[((size_t)b * HID_DIM + k) * OUT_DIM + o];
    }
    g_W2t[idx] = __float2half(v);
}

// ---------------- GEMM: C[rows,N](fp16) = A[rows,K](fp16) @ Bt[N,K]^T(fp16) ----------------
// 256 threads, CTA tile 128x128; row0 = row-block offset (in 128-row units).
__global__ void __launch_bounds__(256)
k_tc_gemm(const __half* __restrict__ A, const __half* __restrict__ Bt,
          __half* __restrict__ C, int Ktot, int N, int row0) {
#if HAS_TCGEN05
    extern __shared__ char smem[];
    const uint32_t sb = smem_u32(smem);
    char* sA = smem + 1024;
    char* sB = smem + 1024 + 32768;
    int tid = threadIdx.x, wid = tid >> 5, lid = tid & 31;
    int rowBase = (blockIdx.y + row0) * 128, colBase = blockIdx.x * 128;

    if (wid == 0) { tmem_alloc(sb, 128); tmem_relinquish(); }
    if (tid == 0) mbar_init(sb + 8, 1);
    __syncthreads();
    uint32_t tmem;
    asm volatile("ld.shared.b32 %0, [%1];" : "=r"(tmem) : "r"(sb));

    const uint32_t idesc = 0x8200010u;
    const uint64_t da = make_desc(sb + 1024);
    const uint64_t db = make_desc(sb + 1024 + 32768);

    int nKc = Ktot >> 7;                     // chunks of 128
    for (int kc = 0; kc < nKc; kc++) {
        if (kc > 0) mbar_wait(sb + 8, (kc - 1) & 1);
        int k0 = kc << 7;
#pragma unroll
        for (int i = 0; i < 8; i++) {
            int fid = i * 256 + tid;
            int r = fid >> 4;
            int c = (fid & 15) * 8;
            uint4 va = *(const uint4*)(A + (size_t)(rowBase + r) * Ktot + k0 + c);
            sts_h8(sA, r, c, va);
            uint4 vb = *(const uint4*)(Bt + (size_t)(colBase + r) * Ktot + k0 + c);
            sts_h8(sB, r, c, vb);
        }
        asm volatile("fence.proxy.async.shared::cta;" ::: "memory");
        __syncthreads();
        if (wid == 0) {
            if (elect_one()) {
#pragma unroll
                for (int ks = 0; ks < 8; ks++) {
                    uint64_t off = (uint64_t)((ks >> 2) * 1024 + (ks & 3) * 2);
                    mma_f16_ss(tmem, da + off, db + off, idesc, (kc | ks) != 0);
                }
                tc_commit(sb + 8);
            }
        }
    }
    mbar_wait(sb + 8, (nKc - 1) & 1);
    asm volatile("tcgen05.fence::after_thread_sync;" ::: "memory");

    // epilogue v2: warp w -> rows (w&3)*32, cols (w>>2)*64; half2-packed staging
    uint32_t* hstg = (uint32_t*)(smem + 1024) + wid * (32 * 33);
    int rowOff = (wid & 3) * 32;
    int colOff = (wid >> 2) * 64;
    uint32_t rg0[32], rg1[32];
    LDTM_X32(rg0, tmem + colOff);
    LDTM_X32(rg1, tmem + colOff + 32);
    asm volatile("tcgen05.wait::ld.sync.aligned;" ::: "memory");
#pragma unroll
    for (int j = 0; j < 16; j++) {
        hstg[lid * 33 + j]      = pack_h2(rg0[2 * j], rg0[2 * j + 1]);
        hstg[lid * 33 + 16 + j] = pack_h2(rg1[2 * j], rg1[2 * j + 1]);
    }
    __syncwarp();
    uint32_t* crow = (uint32_t*)(C + (size_t)(rowBase + rowOff) * N + colBase + colOff);
#pragma unroll 4
    for (int rr = 0; rr < 32; rr++)
        crow[(size_t)rr * (N / 2) + lid] = hstg[rr * 33 + lid];

    asm volatile("tcgen05.fence::before_thread_sync;" ::: "memory");
    __syncthreads();
    if (wid == 0) tmem_dealloc(tmem, 128);
#else
    // ---- SIMT fallback (non-sm_103a passes), correctness only ----
    extern __shared__ char smem[];
    float* As = (float*)smem;
    float* Bs = (float*)smem + 8 * 128;
    int tid = threadIdx.x;
    int rowBase = (blockIdx.y + row0) * 128, colBase = blockIdx.x * 128;
    int tr = (tid >> 4) * 8;
    int tc = (tid & 15) * 8;

    float acc[8][8] = {};
    for (int k0 = 0; k0 < Ktot; k0 += 8) {
        if (tid < 128) {
            uint4 av = *(const uint4*)(A + (size_t)(rowBase + tid) * Ktot + k0);
            const __half2* ah = (const __half2*)&av;
#pragma unroll
            for (int j = 0; j < 4; j++) {
                float2 f = __half22float2(ah[j]);
                As[(2 * j) * 128 + tid] = f.x;
                As[(2 * j + 1) * 128 + tid] = f.y;
            }
        } else {
            int t2 = tid - 128;
            uint4 bv = *(const uint4*)(Bt + (size_t)(colBase + t2) * Ktot + k0);
            const __half2* bh = (const __half2*)&bv;
#pragma unroll
            for (int j = 0; j < 4; j++) {
                float2 f = __half22float2(bh[j]);
                Bs[(2 * j) * 128 + t2] = f.x;
                Bs[(2 * j + 1) * 128 + t2] = f.y;
            }
        }
        __syncthreads();
#pragma unroll
        for (int kk = 0; kk < 8; kk++) {
            float rm[8], rn[8];
#pragma unroll
            for (int i = 0; i < 8; i++) rm[i] = As[kk * 128 + tr + i];
#pragma unroll
            for (int j = 0; j < 8; j++) rn[j] = Bs[kk * 128 + tc + j];
#pragma unroll
            for (int i = 0; i < 8; i++)
#pragma unroll
                for (int j = 0; j < 8; j++) acc[i][j] += rm[i] * rn[j];
        }
        __syncthreads();
    }
#pragma unroll
    for (int i = 0; i < 8; i++) {
        int row = rowBase + tr + i;
#pragma unroll
        for (int j = 0; j < 8; j++)
            C[(size_t)row * N + colBase + tc + j] = __float2half(acc[i][j]);
    }
#endif
}

// ---------------- layer 1: gather-max + root + bias + LN + ReLU -> fp16 h ----------------
__global__ void __launch_bounds__(128) k_agg1(const float* __restrict__ bias,
                                              const float* __restrict__ gamma,
                                              const float* __restrict__ beta,
                                              int n0) {
    int n = blockIdx.x + n0;
    int t = threadIdx.x;
    if (n >= N_NODES) {   // zero pad rows so GEMM2 reads clean data
        ((__half2*)g_h)[(size_t)n * (HID_DIM / 2) + t] = __half2(__half(0.f), __half(0.f));
        return;
    }
    int start = g_offsets[n];
    int deg = g_counts[n];
    const __half2* Y = (const __half2*)g_Y1;

    float mx = -INFINITY, my = -INFINITY;
    int i = 0;
    for (; i + 4 <= deg; i += 4) {
        int r0 = g_rowid[start + i + 0];
        int r1 = g_rowid[start + i + 1];
        int r2 = g_rowid[start + i + 2];
        int r3 = g_rowid[start + i + 3];
        float2 f0 = __half22float2(Y[(size_t)r0 * (HID_DIM / 2) + t]);
        float2 f1 = __half22float2(Y[(size_t)r1 * (HID_DIM / 2) + t]);
        float2 f2 = __half22float2(Y[(size_t)r2 * (HID_DIM / 2) + t]);
        float2 f3 = __half22float2(Y[(size_t)r3 * (HID_DIM / 2) + t]);
        mx = fmaxf(fmaxf(fmaxf(mx, f0.x), fmaxf(f1.x, f2.x)), f3.x);
        my = fmaxf(fmaxf(fmaxf(my, f0.y), fmaxf(f1.y, f2.y)), f3.y);
    }
    for (; i < deg; i++) {
        int row = g_rowid[start + i];
        float2 f = __half22float2(Y[(size_t)row * (HID_DIM / 2) + t]);
        mx = fmaxf(mx, f.x);
        my = fmaxf(my, f.y);
    }
    if (deg == 0) { mx = 0.f; my = 0.f; }

    float2 rootv = __half22float2(Y[((size_t)n * W1_COLS + NREL * HID_DIM) / 2 + t]);
    float2 bi = ((const float2*)bias)[t];
    float vx = mx + rootv.x + bi.x;
    float vy = my + rootv.y + bi.y;

    float s = vx + vy, s2 = vx * vx + vy * vy;
#pragma unroll
    for (int o = 16; o > 0; o >>= 1) {
        s  += __shfl_xor_sync(0xffffffffu, s, o);
        s2 += __shfl_xor_sync(0xffffffffu, s2, o);
    }
    __shared__ float ws[4], ws2[4];
    int w = t >> 5, l = t & 31;
    if (l == 0) { ws[w] = s; ws2[w] = s2; }
    __syncthreads();
    float ts = ws[0] + ws[1] + ws[2] + ws[3];
    float ts2 = ws2[0] + ws2[1] + ws2[2] + ws2[3];
    float mean = ts * (1.f / HID_DIM);
    float var  = ts2 * (1.f / HID_DIM) - mean * mean;
    float rstd = rsqrtf(var + LN_EPS);
    float2 ga = ((const float2*)gamma)[t];
    float2 be = ((const float2*)beta)[t];
    float yx = (vx - mean) * rstd * ga.x + be.x;
    float yy = (vy - mean) * rstd * ga.y + be.y;
    ((__half2*)g_h)[(size_t)n * (HID_DIM / 2) + t] =
        __floats2half2_rn(fmaxf(yx, 0.f), fmaxf(yy, 0.f));
}

// ---------------- layer 2: gather-sum + root + bias + LN + log_softmax ----------------
__global__ void __launch_bounds__(256) k_agg2(const float* __restrict__ bias,
                                              const float* __restrict__ gamma,
                                              const float* __restrict__ beta,
                                              float* __restrict__ out) {
    int n = blockIdx.x * 8 + (threadIdx.x >> 5);
    if (n >= N_NODES) return;
    int lane = threadIdx.x & 31;
    int start = g_offsets[n];
    int deg = g_counts[n];
    const __half2* Y = (const __half2*)g_Y2;

    float sx = 0.f, sy = 0.f;
    int i = 0;
    for (; i + 4 <= deg; i += 4) {
        int r0 = g_rowid[start + i + 0];
        int r1 = g_rowid[start + i + 1];
        int r2 = g_rowid[start + i + 2];
        int r3 = g_rowid[start + i + 3];
        float2 f0 = __half22float2(Y[(size_t)r0 * (OUT_DIM / 2) + lane]);
        float2 f1 = __half22float2(Y[(size_t)r1 * (OUT_DIM / 2) + lane]);
        float2 f2 = __half22float2(Y[(size_t)r2 * (OUT_DIM / 2) + lane]);
        float2 f3 = __half22float2(Y[(size_t)r3 * (OUT_DIM / 2) + lane]);
        sx += (f0.x + f1.x) + (f2.x + f3.x);
        sy += (f0.y + f1.y) + (f2.y + f3.y);
    }
    for (; i < deg; i++) {
        int row = g_rowid[start + i];
        float2 f = __half22float2(Y[(size_t)row * (OUT_DIM / 2) + lane]);
        sx += f.x; sy += f.y;
    }
    float2 rootv = __half22float2(Y[((size_t)n * W2_COLS + NREL * OUT_DIM) / 2 + lane]);
    float2 bi = ((const float2*)bias)[lane];
    float vx = sx + rootv.x + bi.x;
    float vy = sy + rootv.y + bi.y;

    float a = vx + vy, b = vx * vx + vy * vy;
#pragma unroll
    for (int o = 16; o > 0; o >>= 1) {
        a += __shfl_xor_sync(0xffffffffu, a, o);
        b += __shfl_xor_sync(0xffffffffu, b, o);
    }
    float mean = a * (1.f / OUT_DIM);
    float var  = b * (1.f / OUT_DIM) - mean * mean;
    float rstd = rsqrtf(var + LN_EPS);
    float2 ga = ((const float2*)gamma)[lane];
    float2 be = ((const float2*)beta)[lane];
    float yx = (vx - mean) * rstd * ga.x + be.x;
    float yy = (vy - mean) * rstd * ga.y + be.y;

    float mx = fmaxf(yx, yy);
#pragma unroll
    for (int o = 16; o > 0; o >>= 1) mx = fmaxf(mx, __shfl_xor_sync(0xffffffffu, mx, o));
    float es = expf(yx - mx) + expf(yy - mx);
#pragma unroll
    for (int o = 16; o > 0; o >>= 1) es += __shfl_xor_sync(0xffffffffu, es, o);
    float lse = mx + logf(es);

    ((float2*)out)[(size_t)n * (OUT_DIM / 2) + lane] = make_float2(yx - lse, yy - lse);
}

// ---------------- host launch ----------------
extern "C" void kernel_launch(void* const* d_in, const int* in_sizes, int n_in,
                              void* d_out, int out_size) {
    const float* x      = (const float*)d_in[0];
    const int*   ei     = (const int*)d_in[1];
    const int*   et     = (const int*)d_in[2];
    const float* bases1 = (const float*)d_in[3];
    const float* comp1  = (const float*)d_in[4];
    const float* root1  = (const float*)d_in[5];
    const float* bias1  = (const float*)d_in[6];
    const float* g1     = (const float*)d_in[7];
    const float* b1     = (const float*)d_in[8];
    const float* bases2 = (const float*)d_in[9];
    const float* comp2  = (const float*)d_in[10];
    const float* root2  = (const float*)d_in[11];
    const float* bias2  = (const float*)d_in[12];
    const float* g2     = (const float*)d_in[13];
    const float* b2     = (const float*)d_in[14];
    float* out = (float*)d_out;

    __half *pxh, *pW1t, *pW2t, *pY1, *pY2, *ph;
    cudaGetSymbolAddress((void**)&pxh,  g_xh);
    cudaGetSymbolAddress((void**)&pW1t, g_W1t);
    cudaGetSymbolAddress((void**)&pW2t, g_W2t);
    cudaGetSymbolAddress((void**)&pY1,  g_Y1);
    cudaGetSymbolAddress((void**)&pY2,  g_Y2);
    cudaGetSymbolAddress((void**)&ph,   g_h);

    const int SMEM_GEMM = 1024 + 2 * 32768;   // 66560 B
    cudaFuncSetAttribute(k_tc_gemm, cudaFuncAttributeMaxDynamicSharedMemorySize, SMEM_GEMM);

    // lazy one-time stream/event creation (identical work every call)
    static cudaStream_t s2 = nullptr;
    static cudaEvent_t evFork = nullptr, evJoin = nullptr, evA = nullptr, evG2a = nullptr;
    if (s2 == nullptr) {
        cudaStreamCreateWithFlags(&s2, cudaStreamNonBlocking);
        cudaEventCreateWithFlags(&evFork, cudaEventDisableTiming);
        cudaEventCreateWithFlags(&evJoin, cudaEventDisableTiming);
        cudaEventCreateWithFlags(&evA, cudaEventDisableTiming);
        cudaEventCreateWithFlags(&evG2a, cudaEventDisableTiming);
    }

    // fork: CSR chain on s2
    cudaEventRecord(evFork, 0);
    cudaStreamWaitEvent(s2, evFork, 0);

    // --- side stream: CSR build + W2 ---
    k_zero_counts<<<(N_NODES + 255) / 256, 256, 0, s2>>>();
    k_count<<<(N_EDGES + 255) / 256, 256, 0, s2>>>(ei);
    k_scan1<<<SCAN_BLOCKS, 256, 0, s2>>>();
    k_scan2<<<1, 128, 0, s2>>>();
    k_scan3<<<SCAN_BLOCKS, 256, 0, s2>>>();
    k_scatter<<<(N_EDGES + 255) / 256, 256, 0, s2>>>(ei, et);
    k_buildW2t<<<(W2_COLS * HID_DIM + 255) / 256, 256, 0, s2>>>(bases2, comp2, root2);
    cudaEventRecord(evJoin, s2);

    // --- main stream: fused prep (x->fp16 + W1), GEMM1 ---
    k_prep1<<<X2H_BLOCKS + BW1_BLOCKS, 256>>>(x, bases1, comp1, root1);
    {
        dim3 grid(W1_COLS / 128, MPAD / 128);
        k_tc_gemm<<<grid, 256, SMEM_GEMM>>>(pxh, pW1t, pY1, IN_DIM, W1_COLS, 0);
    }

    // join: agg1 needs CSR + Y1 (+ W2 for the GEMM2a launched below)
    cudaStreamWaitEvent(0, evJoin, 0);

    // agg1 chunk 0, then chunk 1 in parallel with GEMM2 chunk 0 on s2
    k_agg1<<<MCHUNK0 * 128, 128>>>(bias1, g1, b1, 0);
    cudaEventRecord(evA, 0);
    cudaStreamWaitEvent(s2, evA, 0);
    {
        dim3 grid(W2_COLS / 128, MCHUNK0);
        k_tc_gemm<<<grid, 256, SMEM_GEMM, s2>>>(ph, pW2t, pY2, HID_DIM, W2_COLS, 0);
    }
    cudaEventRecord(evG2a, s2);

    k_agg1<<<MCHUNK1 * 128, 128>>>(bias1, g1, b1, MCHUNK0 * 128);
    {
        dim3 grid(W2_COLS / 128, MCHUNK1);
        k_tc_gemm<<<grid, 256, SMEM_GEMM>>>(ph, pW2t, pY2, HID_DIM, W2_COLS, MCHUNK0);
    }

    // agg2 needs both GEMM2 halves
    cudaStreamWaitEvent(0, evG2a, 0);
    k_agg2<<<(N_NODES + 7) / 8, 256>>>(bias2, g2, b2, out);
}